// round 8
// baseline (speedup 1.0000x reference)
#include <cuda_runtime.h>
#include <math.h>

// Problem constants
#define B_   2048
#define T_   256
#define DA_  20
// DZ=4, K=3 hardcoded throughout

// Scratch (static __device__ globals -- no allocation in kernel_launch)
__device__ float g_ua[T_ * 8 * B_];        // [t][f][b] : f = u0..u3 (pre-scaled by 1/R), alpha0..2, pad
__device__ float g_fwd[T_ * 56 * B_];      // [t][f][b] : 0-3 z_hat, 4-19 std_hat_clipped, 20-35 Ai, 36-39 post_z, 40-55 post_std
__device__ float g_M[96];                  // 6 combined Gram matrices (4x4 each): G00,G11,G22,G01+G10,G02+G20,G12+G21

// ---------------------------------------------------------------------------
// 4x4 helpers (row-major flat arrays)
// ---------------------------------------------------------------------------
__device__ __forceinline__ void mm4(const float* A, const float* B, float* C) {
#pragma unroll
    for (int i = 0; i < 4; i++)
#pragma unroll
        for (int j = 0; j < 4; j++) {
            float s = A[i*4+0] * B[0*4+j];
            s = fmaf(A[i*4+1], B[1*4+j], s);
            s = fmaf(A[i*4+2], B[2*4+j], s);
            s = fmaf(A[i*4+3], B[3*4+j], s);
            C[i*4+j] = s;
        }
}

// C = A * B^T
__device__ __forceinline__ void mmT4(const float* A, const float* B, float* C) {
#pragma unroll
    for (int i = 0; i < 4; i++)
#pragma unroll
        for (int j = 0; j < 4; j++) {
            float s = A[i*4+0] * B[j*4+0];
            s = fmaf(A[i*4+1], B[j*4+1], s);
            s = fmaf(A[i*4+2], B[j*4+2], s);
            s = fmaf(A[i*4+3], B[j*4+3], s);
            C[i*4+j] = s;
        }
}

__device__ __forceinline__ void mv4(const float* A, const float* x, float* y) {
#pragma unroll
    for (int i = 0; i < 4; i++) {
        float s = A[i*4+0] * x[0];
        s = fmaf(A[i*4+1], x[1], s);
        s = fmaf(A[i*4+2], x[2], s);
        s = fmaf(A[i*4+3], x[3], s);
        y[i] = s;
    }
}

// Branch-free 4x4 inverse via 2x2 sub-determinants (gl-matrix form;
// layout-agnostic for flat arrays).
__device__ __forceinline__ void inv4(const float* a, float* inv) {
    float b00 = a[0]*a[5]  - a[1]*a[4];
    float b01 = a[0]*a[6]  - a[2]*a[4];
    float b02 = a[0]*a[7]  - a[3]*a[4];
    float b03 = a[1]*a[6]  - a[2]*a[5];
    float b04 = a[1]*a[7]  - a[3]*a[5];
    float b05 = a[2]*a[7]  - a[3]*a[6];
    float b06 = a[8]*a[13] - a[9]*a[12];
    float b07 = a[8]*a[14] - a[10]*a[12];
    float b08 = a[8]*a[15] - a[11]*a[12];
    float b09 = a[9]*a[14] - a[10]*a[13];
    float b10 = a[9]*a[15] - a[11]*a[13];
    float b11 = a[10]*a[15]- a[11]*a[14];
    float det = b00*b11 - b01*b10 + b02*b09 + b03*b08 - b04*b07 + b05*b06;
    float id = 1.0f / det;
    inv[0]  = (a[5]*b11  - a[6]*b10  + a[7]*b09 ) * id;
    inv[1]  = (a[2]*b10  - a[1]*b11  - a[3]*b09 ) * id;
    inv[2]  = (a[13]*b05 - a[14]*b04 + a[15]*b03) * id;
    inv[3]  = (a[10]*b04 - a[9]*b05  - a[11]*b03) * id;
    inv[4]  = (a[6]*b08  - a[4]*b11  - a[7]*b07 ) * id;
    inv[5]  = (a[0]*b11  - a[2]*b08  + a[3]*b07 ) * id;
    inv[6]  = (a[14]*b02 - a[12]*b05 - a[15]*b01) * id;
    inv[7]  = (a[8]*b05  - a[10]*b02 + a[11]*b01) * id;
    inv[8]  = (a[4]*b10  - a[5]*b08  + a[7]*b06 ) * id;
    inv[9]  = (a[1]*b08  - a[0]*b10  - a[3]*b06 ) * id;
    inv[10] = (a[12]*b04 - a[13]*b02 + a[15]*b00) * id;
    inv[11] = (a[9]*b02  - a[8]*b04  - a[11]*b00) * id;
    inv[12] = (a[5]*b07  - a[4]*b09  - a[6]*b06 ) * id;
    inv[13] = (a[0]*b09  - a[1]*b07  + a[2]*b06 ) * id;
    inv[14] = (a[13]*b01 - a[12]*b03 - a[14]*b00) * id;
    inv[15] = (a[8]*b03  - a[9]*b01  + a[10]*b00) * id;
}

// ---------------------------------------------------------------------------
// Kernel 1: Gram combinations of C_base (batch/time independent)
// g_M[m][j1*4+j2]: m=0..2 -> Ck^T Ck ; m=3..5 -> Ck^T Cl + Cl^T Ck for (0,1),(0,2),(1,2)
// ---------------------------------------------------------------------------
__global__ void gram_kernel(const float* __restrict__ Cb) {
    int tid = threadIdx.x;
    if (tid >= 96) return;
    int m = tid >> 4, idx = tid & 15, j1 = idx >> 2, j2 = idx & 3;
    int k, l;
    switch (m) {
        case 0: k = 0; l = 0; break;
        case 1: k = 1; l = 1; break;
        case 2: k = 2; l = 2; break;
        case 3: k = 0; l = 1; break;
        case 4: k = 0; l = 2; break;
        default: k = 1; l = 2; break;
    }
    float s = 0.0f;
    for (int i = 0; i < DA_; i++)
        s = fmaf(Cb[k*80 + i*4 + j1], Cb[l*80 + i*4 + j2], s);
    if (k != l) {
        for (int i = 0; i < DA_; i++)
            s = fmaf(Cb[l*80 + i*4 + j1], Cb[k*80 + i*4 + j2], s);
    }
    g_M[m*16 + idx] = s;
}

// ---------------------------------------------------------------------------
// Kernel 2: per-(b,t) precompute: alpha = softmax(logits), u = Ci^T a / R
// ---------------------------------------------------------------------------
__global__ void pre_kernel(const float* __restrict__ a,
                           const float* __restrict__ lg,
                           const float* __restrict__ Cb) {
    __shared__ float sC[240];
    for (int i = threadIdx.x; i < 240; i += blockDim.x) sC[i] = Cb[i];
    __syncthreads();

    int tid = blockIdx.x * blockDim.x + threadIdx.x;
    int t = tid / B_;
    int b = tid - t * B_;
    if (t >= T_) return;

    const float* lp = lg + ((size_t)b * T_ + t) * 3;
    float l0 = lp[0], l1 = lp[1], l2 = lp[2];
    float mx = fmaxf(l0, fmaxf(l1, l2));
    float e0 = expf(l0 - mx), e1 = expf(l1 - mx), e2 = expf(l2 - mx);
    float is = 1.0f / (e0 + e1 + e2);
    float a0 = e0 * is, a1 = e1 * is, a2 = e2 * is;

    const float* ap = a + ((size_t)b * T_ + t) * DA_;
    float u0 = 0.f, u1 = 0.f, u2 = 0.f, u3 = 0.f;
#pragma unroll
    for (int i = 0; i < DA_; i++) {
        float av = ap[i];
        float w0 = fmaf(a0, sC[i*4+0], fmaf(a1, sC[80+i*4+0], a2 * sC[160+i*4+0]));
        float w1 = fmaf(a0, sC[i*4+1], fmaf(a1, sC[80+i*4+1], a2 * sC[160+i*4+1]));
        float w2 = fmaf(a0, sC[i*4+2], fmaf(a1, sC[80+i*4+2], a2 * sC[160+i*4+2]));
        float w3 = fmaf(a0, sC[i*4+3], fmaf(a1, sC[80+i*4+3], a2 * sC[160+i*4+3]));
        u0 = fmaf(av, w0, u0);
        u1 = fmaf(av, w1, u1);
        u2 = fmaf(av, w2, u2);
        u3 = fmaf(av, w3, u3);
    }
    const float rinv = 1.0f / 0.03f;
    int base = t * 8 * B_ + b;
    g_ua[base + 0*B_] = u0 * rinv;
    g_ua[base + 1*B_] = u1 * rinv;
    g_ua[base + 2*B_] = u2 * rinv;
    g_ua[base + 3*B_] = u3 * rinv;
    g_ua[base + 4*B_] = a0;
    g_ua[base + 5*B_] = a1;
    g_ua[base + 6*B_] = a2;
}

// ---------------------------------------------------------------------------
// Kernel 3: sequential Kalman filter (information-form update, all 4x4) +
//           backward RTS smoother. One thread per batch element.
// ---------------------------------------------------------------------------
__global__ void __launch_bounds__(32, 1)
seq_kernel(const float* __restrict__ Ab, float* __restrict__ out) {
    __shared__ float sA[48];
    __shared__ float sM[96];
    for (int i = threadIdx.x; i < 48; i += 32) sA[i] = Ab[i];
    for (int i = threadIdx.x; i < 96; i += 32) sM[i] = g_M[i];
    __syncthreads();

    int b = blockIdx.x * 32 + threadIdx.x;
    const float rinv = 1.0f / 0.03f;
    const float Qd = 0.08f;

    float z[4] = {0.f, 0.f, 0.f, 0.f};
    float P[16];
#pragma unroll
    for (int i = 0; i < 16; i++) P[i] = (i % 5 == 0) ? 20.0f : 0.0f;

    // -------- forward filter --------
    for (int t = 0; t < T_; t++) {
        int base = t * 8 * B_ + b;
        float ur[4];
        ur[0] = g_ua[base + 0*B_];
        ur[1] = g_ua[base + 1*B_];
        ur[2] = g_ua[base + 2*B_];
        ur[3] = g_ua[base + 3*B_];
        float al0 = g_ua[base + 4*B_];
        float al1 = g_ua[base + 5*B_];
        float al2 = g_ua[base + 6*B_];

        // Cr = (Ci^T Ci) / R from the 6 Gram combos; Ai = sum alpha_k A_k
        float c0 = al0*al0*rinv, c1 = al1*al1*rinv, c2 = al2*al2*rinv;
        float c3 = al0*al1*rinv, c4 = al0*al2*rinv, c5 = al1*al2*rinv;
        float Ai[16], Cr[16];
#pragma unroll
        for (int i = 0; i < 16; i++) {
            Ai[i] = fmaf(al0, sA[i], fmaf(al1, sA[16+i], al2 * sA[32+i]));
            Cr[i] = fmaf(c0, sM[i],
                    fmaf(c1, sM[16+i],
                    fmaf(c2, sM[32+i],
                    fmaf(c3, sM[48+i],
                    fmaf(c4, sM[64+i], c5 * sM[80+i])))));
        }

        // predict
        float zh[4]; mv4(Ai, z, zh);
        float AP[16]; mm4(Ai, P, AP);
        float Ph[16]; mmT4(AP, Ai, Ph);       // Ai P Ai^T
        Ph[0] += Qd; Ph[5] += Qd; Ph[10] += Qd; Ph[15] += Qd;

        // clipped std_hat (used only by the smoother)
        float shc[16];
#pragma unroll
        for (int i = 0; i < 16; i++)
            shc[i] = fmaxf(Ph[i], (i % 5 == 0) ? 1e-4f : 0.0f);

        // update (Woodbury): W = (Ph^-1 + CtC/R)^-1 = (I + Ph*Cr)^-1 * Ph
        float E[16]; mm4(Ph, Cr, E);
        E[0] += 1.f; E[5] += 1.f; E[10] += 1.f; E[15] += 1.f;
        float Ei[16]; inv4(E, Ei);
        float W[16]; mm4(Ei, Ph, W);

        // post_z = zh + W*(u/R - Cr*zh)   [= zh + Kg*resid]
        float y[4]; mv4(Cr, zh, y);
#pragma unroll
        for (int i = 0; i < 4; i++) y[i] = ur[i] - y[i];
        float dz[4]; mv4(W, y, dz);
        float pz[4];
#pragma unroll
        for (int i = 0; i < 4; i++) pz[i] = zh[i] + dz[i];

        // T1 = Kg*Ci = W*Cr ; IKC = I - T1
        float T1[16]; mm4(W, Cr, T1);
        float IK[16];
#pragma unroll
        for (int i = 0; i < 16; i++)
            IK[i] = ((i % 5 == 0) ? 1.0f : 0.0f) - T1[i];

        // post_std = IKC Ph IKC^T + Kg R Kg^T, with Kg R Kg^T = T1 * W^T
        float Gm[16]; mm4(IK, Ph, Gm);
        float X[16];  mmT4(Gm, IK, X);
        float Y2[16]; mmT4(T1, W, Y2);
        float ps[16];
#pragma unroll
        for (int i = 0; i < 16; i++) ps[i] = X[i] + Y2[i];

        // store filter outputs (coalesced: [t][f][b])
        int fb = t * 56 * B_ + b;
#pragma unroll
        for (int i = 0; i < 4; i++)  g_fwd[fb + i*B_]        = zh[i];
#pragma unroll
        for (int i = 0; i < 16; i++) g_fwd[fb + (4+i)*B_]    = shc[i];
#pragma unroll
        for (int i = 0; i < 16; i++) g_fwd[fb + (20+i)*B_]   = Ai[i];
#pragma unroll
        for (int i = 0; i < 4; i++)  g_fwd[fb + (36+i)*B_]   = pz[i];
#pragma unroll
        for (int i = 0; i < 16; i++) g_fwd[fb + (40+i)*B_]   = ps[i];

#pragma unroll
        for (int i = 0; i < 4; i++)  z[i] = pz[i];
#pragma unroll
        for (int i = 0; i < 16; i++) P[i] = ps[i];
    }

    // -------- backward RTS smoother --------
    float* oz = out;                                   // z_smooth  [B,T,4]
    float* os = out + (size_t)B_ * T_ * 4;             // std_smooth [B,T,4,4]

    float zs[4], ss[16];
#pragma unroll
    for (int i = 0; i < 4; i++) zs[i] = z[i];
#pragma unroll
    for (int i = 0; i < 16; i++) ss[i] = P[i];
    {
        size_t zo = ((size_t)b * T_ + (T_ - 1)) * 4;
        size_t so = ((size_t)b * T_ + (T_ - 1)) * 16;
#pragma unroll
        for (int i = 0; i < 4; i++)  oz[zo + i] = zs[i];
#pragma unroll
        for (int i = 0; i < 16; i++) os[so + i] = ss[i];
    }

    for (int t = T_ - 2; t >= 0; t--) {
        int fn = (t + 1) * 56 * B_ + b;
        int fc = t * 56 * B_ + b;
        float zhn[4], shn[16], Ain[16], pz[4], ps[16];
#pragma unroll
        for (int i = 0; i < 4; i++)  zhn[i] = g_fwd[fn + i*B_];
#pragma unroll
        for (int i = 0; i < 16; i++) shn[i] = g_fwd[fn + (4+i)*B_];
#pragma unroll
        for (int i = 0; i < 16; i++) Ain[i] = g_fwd[fn + (20+i)*B_];
#pragma unroll
        for (int i = 0; i < 4; i++)  pz[i]  = g_fwd[fc + (36+i)*B_];
#pragma unroll
        for (int i = 0; i < 16; i++) ps[i]  = g_fwd[fc + (40+i)*B_];

        float inv[16]; inv4(shn, inv);
        float PA[16];  mmT4(ps, Ain, PA);     // post_std * A^T
        float D[16];   mm4(PA, inv, D);

        float dv[4];
#pragma unroll
        for (int i = 0; i < 4; i++) dv[i] = zs[i] - zhn[i];
        float tz[4]; mv4(D, dv, tz);

        float dS[16];
#pragma unroll
        for (int i = 0; i < 16; i++) dS[i] = ss[i] - shn[i];
        float DD[16];  mm4(D, dS, DD);
        float DS2[16]; mmT4(DD, D, DS2);

#pragma unroll
        for (int i = 0; i < 4; i++)  zs[i] = pz[i] + tz[i];
#pragma unroll
        for (int i = 0; i < 16; i++) ss[i] = ps[i] + DS2[i];

        size_t zo = ((size_t)b * T_ + t) * 4;
        size_t so = ((size_t)b * T_ + t) * 16;
#pragma unroll
        for (int i = 0; i < 4; i++)  oz[zo + i] = zs[i];
#pragma unroll
        for (int i = 0; i < 16; i++) os[so + i] = ss[i];
    }
}

// ---------------------------------------------------------------------------
extern "C" void kernel_launch(void* const* d_in, const int* in_sizes, int n_in,
                              void* d_out, int out_size) {
    const float* a  = (const float*)d_in[0];   // [B,T,20]
    const float* lg = (const float*)d_in[1];   // [B,T,3]
    const float* Ab = (const float*)d_in[2];   // [3,4,4]
    const float* Cb = (const float*)d_in[3];   // [3,20,4]
    float* out = (float*)d_out;

    gram_kernel<<<1, 96>>>(Cb);
    pre_kernel<<<(B_ * T_) / 256, 256>>>(a, lg, Cb);
    seq_kernel<<<B_ / 32, 32>>>(Ab, out);
}

// round 9
// speedup vs baseline: 2.5891x; 2.5891x over previous
#include <cuda_runtime.h>
#include <math.h>

// Problem constants
#define B_   2048
#define T_   256
#define DA_  20
// DZ=4, K=3 hardcoded throughout

// Scratch (static __device__ globals -- no allocation in kernel_launch)
__device__ float g_ua[T_ * 8 * B_];        // [t][f][b] : f = u0..u3 (pre-scaled by 1/R), alpha0..2, pad
__device__ float g_fwd[T_ * 14 * B_];      // [t][f][b] : 0-3 post_z, 4-13 post_std (sym10)

// ---------------------------------------------------------------------------
// 4x4 helpers (row-major flat arrays)
// ---------------------------------------------------------------------------
__device__ __forceinline__ void mm4(const float* A, const float* B, float* C) {
#pragma unroll
    for (int i = 0; i < 4; i++)
#pragma unroll
        for (int j = 0; j < 4; j++) {
            float s = A[i*4+0] * B[0*4+j];
            s = fmaf(A[i*4+1], B[1*4+j], s);
            s = fmaf(A[i*4+2], B[2*4+j], s);
            s = fmaf(A[i*4+3], B[3*4+j], s);
            C[i*4+j] = s;
        }
}

// C = A * B^T, result known symmetric (or B symmetric so A*B symmetric):
// compute upper triangle only, mirror.
__device__ __forceinline__ void mmT4_sym(const float* A, const float* B, float* C) {
#pragma unroll
    for (int i = 0; i < 4; i++)
#pragma unroll
        for (int j = i; j < 4; j++) {
            float s = A[i*4+0] * B[j*4+0];
            s = fmaf(A[i*4+1], B[j*4+1], s);
            s = fmaf(A[i*4+2], B[j*4+2], s);
            s = fmaf(A[i*4+3], B[j*4+3], s);
            C[i*4+j] = s;
        }
    C[4]  = C[1];  C[8]  = C[2];  C[12] = C[3];
    C[9]  = C[6];  C[13] = C[7];  C[14] = C[11];
}

__device__ __forceinline__ void mv4(const float* A, const float* x, float* y) {
#pragma unroll
    for (int i = 0; i < 4; i++) {
        float s = A[i*4+0] * x[0];
        s = fmaf(A[i*4+1], x[1], s);
        s = fmaf(A[i*4+2], x[2], s);
        s = fmaf(A[i*4+3], x[3], s);
        y[i] = s;
    }
}

// Branch-free 4x4 inverse via 2x2 sub-determinants.
__device__ __forceinline__ void inv4(const float* a, float* inv) {
    float b00 = a[0]*a[5]  - a[1]*a[4];
    float b01 = a[0]*a[6]  - a[2]*a[4];
    float b02 = a[0]*a[7]  - a[3]*a[4];
    float b03 = a[1]*a[6]  - a[2]*a[5];
    float b04 = a[1]*a[7]  - a[3]*a[5];
    float b05 = a[2]*a[7]  - a[3]*a[6];
    float b06 = a[8]*a[13] - a[9]*a[12];
    float b07 = a[8]*a[14] - a[10]*a[12];
    float b08 = a[8]*a[15] - a[11]*a[12];
    float b09 = a[9]*a[14] - a[10]*a[13];
    float b10 = a[9]*a[15] - a[11]*a[13];
    float b11 = a[10]*a[15]- a[11]*a[14];
    float det = b00*b11 - b01*b10 + b02*b09 + b03*b08 - b04*b07 + b05*b06;
    float id = 1.0f / det;
    inv[0]  = (a[5]*b11  - a[6]*b10  + a[7]*b09 ) * id;
    inv[1]  = (a[2]*b10  - a[1]*b11  - a[3]*b09 ) * id;
    inv[2]  = (a[13]*b05 - a[14]*b04 + a[15]*b03) * id;
    inv[3]  = (a[10]*b04 - a[9]*b05  - a[11]*b03) * id;
    inv[4]  = (a[6]*b08  - a[4]*b11  - a[7]*b07 ) * id;
    inv[5]  = (a[0]*b11  - a[2]*b08  + a[3]*b07 ) * id;
    inv[6]  = (a[14]*b02 - a[12]*b05 - a[15]*b01) * id;
    inv[7]  = (a[8]*b05  - a[10]*b02 + a[11]*b01) * id;
    inv[8]  = (a[4]*b10  - a[5]*b08  + a[7]*b06 ) * id;
    inv[9]  = (a[1]*b08  - a[0]*b10  - a[3]*b06 ) * id;
    inv[10] = (a[12]*b04 - a[13]*b02 + a[15]*b00) * id;
    inv[11] = (a[9]*b02  - a[8]*b04  - a[11]*b00) * id;
    inv[12] = (a[5]*b07  - a[4]*b09  - a[6]*b06 ) * id;
    inv[13] = (a[0]*b09  - a[1]*b07  + a[2]*b06 ) * id;
    inv[14] = (a[13]*b01 - a[12]*b03 - a[14]*b00) * id;
    inv[15] = (a[8]*b03  - a[9]*b01  + a[10]*b00) * id;
}

// ---------------------------------------------------------------------------
// Kernel 1: per-(b,t) precompute: alpha = softmax(logits), u = Ci^T a / R
// ---------------------------------------------------------------------------
__global__ void pre_kernel(const float* __restrict__ a,
                           const float* __restrict__ lg,
                           const float* __restrict__ Cb) {
    __shared__ float sC[240];
    for (int i = threadIdx.x; i < 240; i += blockDim.x) sC[i] = Cb[i];
    __syncthreads();

    int tid = blockIdx.x * blockDim.x + threadIdx.x;
    int t = tid / B_;
    int b = tid - t * B_;
    if (t >= T_) return;

    const float* lp = lg + ((size_t)b * T_ + t) * 3;
    float l0 = lp[0], l1 = lp[1], l2 = lp[2];
    float mx = fmaxf(l0, fmaxf(l1, l2));
    float e0 = expf(l0 - mx), e1 = expf(l1 - mx), e2 = expf(l2 - mx);
    float is = 1.0f / (e0 + e1 + e2);
    float a0 = e0 * is, a1 = e1 * is, a2 = e2 * is;

    // vectorized load of a_t (20 floats, 16B aligned: stride 80B)
    const float4* ap4 = reinterpret_cast<const float4*>(a + ((size_t)b * T_ + t) * DA_);
    float av[20];
#pragma unroll
    for (int q = 0; q < 5; q++) {
        float4 v = ap4[q];
        av[q*4+0] = v.x; av[q*4+1] = v.y; av[q*4+2] = v.z; av[q*4+3] = v.w;
    }

    float u0 = 0.f, u1 = 0.f, u2 = 0.f, u3 = 0.f;
#pragma unroll
    for (int i = 0; i < DA_; i++) {
        float w0 = fmaf(a0, sC[i*4+0], fmaf(a1, sC[80+i*4+0], a2 * sC[160+i*4+0]));
        float w1 = fmaf(a0, sC[i*4+1], fmaf(a1, sC[80+i*4+1], a2 * sC[160+i*4+1]));
        float w2 = fmaf(a0, sC[i*4+2], fmaf(a1, sC[80+i*4+2], a2 * sC[160+i*4+2]));
        float w3 = fmaf(a0, sC[i*4+3], fmaf(a1, sC[80+i*4+3], a2 * sC[160+i*4+3]));
        u0 = fmaf(av[i], w0, u0);
        u1 = fmaf(av[i], w1, u1);
        u2 = fmaf(av[i], w2, u2);
        u3 = fmaf(av[i], w3, u3);
    }
    const float rinv = 1.0f / 0.03f;
    int base = t * 8 * B_ + b;
    g_ua[base + 0*B_] = u0 * rinv;
    g_ua[base + 1*B_] = u1 * rinv;
    g_ua[base + 2*B_] = u2 * rinv;
    g_ua[base + 3*B_] = u3 * rinv;
    g_ua[base + 4*B_] = a0;
    g_ua[base + 5*B_] = a1;
    g_ua[base + 6*B_] = a2;
}

// ---------------------------------------------------------------------------
// Output store helper (vectorized)
// ---------------------------------------------------------------------------
__device__ __forceinline__ void store_out(int b, int t, const float* zs,
                                          const float* ss, float* out) {
    float* oz = out + ((size_t)b * T_ + t) * 4;
    *reinterpret_cast<float4*>(oz) = make_float4(zs[0], zs[1], zs[2], zs[3]);
    float* os = out + (size_t)B_ * T_ * 4 + ((size_t)b * T_ + t) * 16;
#pragma unroll
    for (int r = 0; r < 4; r++)
        reinterpret_cast<float4*>(os)[r] =
            make_float4(ss[r*4+0], ss[r*4+1], ss[r*4+2], ss[r*4+3]);
}

// ---------------------------------------------------------------------------
// Kernel 2: sequential Kalman filter (Woodbury posterior, all 4x4, symmetric
// fast paths) + backward RTS smoother. One thread per batch element.
// ---------------------------------------------------------------------------
__global__ void __launch_bounds__(32)
seq_kernel(const float* __restrict__ Ab, const float* __restrict__ Cb,
           float* __restrict__ out) {
    __shared__ float sA[48];
    __shared__ float sM[96];   // 6 combined Gram matrices of C_base

    // Fold the Gram precompute into setup (tiny; removes a kernel launch).
    for (int e = threadIdx.x; e < 96; e += 32) {
        int m = e >> 4, idx = e & 15, j1 = idx >> 2, j2 = idx & 3;
        int k, l;
        switch (m) {
            case 0: k = 0; l = 0; break;
            case 1: k = 1; l = 1; break;
            case 2: k = 2; l = 2; break;
            case 3: k = 0; l = 1; break;
            case 4: k = 0; l = 2; break;
            default: k = 1; l = 2; break;
        }
        float s = 0.0f;
        for (int i = 0; i < DA_; i++)
            s = fmaf(Cb[k*80 + i*4 + j1], Cb[l*80 + i*4 + j2], s);
        if (k != l)
            for (int i = 0; i < DA_; i++)
                s = fmaf(Cb[l*80 + i*4 + j1], Cb[k*80 + i*4 + j2], s);
        sM[e] = s;
    }
    for (int i = threadIdx.x; i < 48; i += 32) sA[i] = Ab[i];
    __syncthreads();

    const int b = blockIdx.x * 32 + threadIdx.x;
    const float rinv = 1.0f / 0.03f;
    const float Qd = 0.08f;
    const int SI[10] = {0, 1, 2, 3, 5, 6, 7, 10, 11, 15};

    float z[4] = {0.f, 0.f, 0.f, 0.f};
    float P[16];
#pragma unroll
    for (int i = 0; i < 16; i++) P[i] = (i % 5 == 0) ? 20.0f : 0.0f;

    // -------- forward filter --------
    float ur[4], al[3];
    {   // preload t=0
        int base = 0 * 8 * B_ + b;
#pragma unroll
        for (int i = 0; i < 4; i++) ur[i] = g_ua[base + i*B_];
#pragma unroll
        for (int i = 0; i < 3; i++) al[i] = g_ua[base + (4+i)*B_];
    }

    for (int t = 0; t < T_; t++) {
        // prefetch next step's inputs (hide L2 latency under FMA chain)
        float urn[4], aln[3];
        if (t + 1 < T_) {
            int nb = (t + 1) * 8 * B_ + b;
#pragma unroll
            for (int i = 0; i < 4; i++) urn[i] = g_ua[nb + i*B_];
#pragma unroll
            for (int i = 0; i < 3; i++) aln[i] = g_ua[nb + (4+i)*B_];
        }

        // Ai = sum alpha_k A_k ; Cr = Ci^T Ci / R (symmetric, 6 Gram combos)
        float c0 = al[0]*al[0]*rinv, c1 = al[1]*al[1]*rinv, c2 = al[2]*al[2]*rinv;
        float c3 = al[0]*al[1]*rinv, c4 = al[0]*al[2]*rinv, c5 = al[1]*al[2]*rinv;
        float Ai[16], Cr[16];
#pragma unroll
        for (int i = 0; i < 16; i++)
            Ai[i] = fmaf(al[0], sA[i], fmaf(al[1], sA[16+i], al[2] * sA[32+i]));
#pragma unroll
        for (int u = 0; u < 10; u++) {
            int i = SI[u];
            Cr[i] = fmaf(c0, sM[i],
                    fmaf(c1, sM[16+i],
                    fmaf(c2, sM[32+i],
                    fmaf(c3, sM[48+i],
                    fmaf(c4, sM[64+i], c5 * sM[80+i])))));
        }
        Cr[4]  = Cr[1];  Cr[8]  = Cr[2];  Cr[12] = Cr[3];
        Cr[9]  = Cr[6];  Cr[13] = Cr[7];  Cr[14] = Cr[11];

        // predict
        float zh[4]; mv4(Ai, z, zh);
        float AP[16]; mm4(Ai, P, AP);
        float Ph[16]; mmT4_sym(AP, Ai, Ph);       // Ai P Ai^T (symmetric)
        Ph[0] += Qd; Ph[5] += Qd; Ph[10] += Qd; Ph[15] += Qd;

        // update (Woodbury): post_std = W = (I + Ph*Cr)^-1 * Ph
        float E[16]; mm4(Ph, Cr, E);
        E[0] += 1.f; E[5] += 1.f; E[10] += 1.f; E[15] += 1.f;
        float Ei[16]; inv4(E, Ei);
        float W[16]; mmT4_sym(Ei, Ph, W);         // Ei * Ph (Ph sym -> use rows)

        // post_z = zh + W*(u/R - Cr*zh)
        float y[4]; mv4(Cr, zh, y);
#pragma unroll
        for (int i = 0; i < 4; i++) y[i] = ur[i] - y[i];
        float dz[4]; mv4(W, y, dz);
        float pz[4];
#pragma unroll
        for (int i = 0; i < 4; i++) pz[i] = zh[i] + dz[i];

        // store posterior only (coalesced: [t][f][b]); backward recomputes the rest
        int fb = t * 14 * B_ + b;
#pragma unroll
        for (int i = 0; i < 4; i++)  g_fwd[fb + i*B_]     = pz[i];
#pragma unroll
        for (int u = 0; u < 10; u++) g_fwd[fb + (4+u)*B_] = W[SI[u]];

#pragma unroll
        for (int i = 0; i < 4; i++)  z[i] = pz[i];
#pragma unroll
        for (int i = 0; i < 16; i++) P[i] = W[i];
#pragma unroll
        for (int i = 0; i < 4; i++) ur[i] = urn[i];
#pragma unroll
        for (int i = 0; i < 3; i++) al[i] = aln[i];
    }

    // -------- backward RTS smoother --------
    float zs[4], ss[16];
#pragma unroll
    for (int i = 0; i < 4; i++) zs[i] = z[i];
#pragma unroll
    for (int i = 0; i < 16; i++) ss[i] = P[i];
    store_out(b, T_ - 1, zs, ss, out);

    // preload step t = T-2: pz_t, ps_t, alpha_{t+1}
    float cpz[4], cps[16], cal[3];
    {
        int fb = (T_ - 2) * 14 * B_ + b;
#pragma unroll
        for (int i = 0; i < 4; i++) cpz[i] = g_fwd[fb + i*B_];
        float p10[10];
#pragma unroll
        for (int u = 0; u < 10; u++) p10[u] = g_fwd[fb + (4+u)*B_];
#pragma unroll
        for (int u = 0; u < 10; u++) cps[SI[u]] = p10[u];
        cps[4]  = cps[1];  cps[8]  = cps[2];  cps[12] = cps[3];
        cps[9]  = cps[6];  cps[13] = cps[7];  cps[14] = cps[11];
        int ub = (T_ - 1) * 8 * B_ + b;
#pragma unroll
        for (int i = 0; i < 3; i++) cal[i] = g_ua[ub + (4+i)*B_];
    }

    for (int t = T_ - 2; t >= 0; t--) {
        // prefetch t-1 inputs
        float npz[4], nps[16], nal[3];
        if (t > 0) {
            int fb = (t - 1) * 14 * B_ + b;
#pragma unroll
            for (int i = 0; i < 4; i++) npz[i] = g_fwd[fb + i*B_];
            float p10[10];
#pragma unroll
            for (int u = 0; u < 10; u++) p10[u] = g_fwd[fb + (4+u)*B_];
#pragma unroll
            for (int u = 0; u < 10; u++) nps[SI[u]] = p10[u];
            nps[4]  = nps[1];  nps[8]  = nps[2];  nps[12] = nps[3];
            nps[9]  = nps[6];  nps[13] = nps[7];  nps[14] = nps[11];
            int ub = t * 8 * B_ + b;
#pragma unroll
            for (int i = 0; i < 3; i++) nal[i] = g_ua[ub + (4+i)*B_];
        }

        // recompute A_{t+1}, z_hat_{t+1}, clipped std_hat_{t+1} (bit-identical
        // to the forward pass, cheaper than storing/loading them)
        float Ai[16];
#pragma unroll
        for (int i = 0; i < 16; i++)
            Ai[i] = fmaf(cal[0], sA[i], fmaf(cal[1], sA[16+i], cal[2] * sA[32+i]));
        float zhn[4]; mv4(Ai, cpz, zhn);
        float APs[16]; mm4(Ai, cps, APs);
        float shn[16]; mmT4_sym(APs, Ai, shn);
        shn[0] += Qd; shn[5] += Qd; shn[10] += Qd; shn[15] += Qd;
#pragma unroll
        for (int i = 0; i < 16; i++)
            shn[i] = fmaxf(shn[i], (i % 5 == 0) ? 1e-4f : 0.0f);

        float inv[16]; inv4(shn, inv);
        // D = ps * A^T * inv = APs^T * inv  (ps symmetric -> ps*A^T = (A*ps)^T)
        float D[16];
#pragma unroll
        for (int i = 0; i < 4; i++)
#pragma unroll
            for (int j = 0; j < 4; j++) {
                float s = APs[0*4+i] * inv[0*4+j];
                s = fmaf(APs[1*4+i], inv[1*4+j], s);
                s = fmaf(APs[2*4+i], inv[2*4+j], s);
                s = fmaf(APs[3*4+i], inv[3*4+j], s);
                D[i*4+j] = s;
            }

        float dv[4];
#pragma unroll
        for (int i = 0; i < 4; i++) dv[i] = zs[i] - zhn[i];
        float tz[4]; mv4(D, dv, tz);

        float dS[16];
#pragma unroll
        for (int i = 0; i < 16; i++) dS[i] = ss[i] - shn[i];
        float DD[16];  mm4(D, dS, DD);
        float DS2[16]; mmT4_sym(DD, D, DS2);

#pragma unroll
        for (int i = 0; i < 4; i++)  zs[i] = cpz[i] + tz[i];
#pragma unroll
        for (int i = 0; i < 16; i++) ss[i] = cps[i] + DS2[i];

        store_out(b, t, zs, ss, out);

#pragma unroll
        for (int i = 0; i < 4; i++)  cpz[i] = npz[i];
#pragma unroll
        for (int i = 0; i < 16; i++) cps[i] = nps[i];
#pragma unroll
        for (int i = 0; i < 3; i++)  cal[i] = nal[i];
    }
}

// ---------------------------------------------------------------------------
extern "C" void kernel_launch(void* const* d_in, const int* in_sizes, int n_in,
                              void* d_out, int out_size) {
    const float* a  = (const float*)d_in[0];   // [B,T,20]
    const float* lg = (const float*)d_in[1];   // [B,T,3]
    const float* Ab = (const float*)d_in[2];   // [3,4,4]
    const float* Cb = (const float*)d_in[3];   // [3,20,4]
    float* out = (float*)d_out;

    pre_kernel<<<(B_ * T_) / 256, 256>>>(a, lg, Cb);
    seq_kernel<<<B_ / 32, 32>>>(Ab, Cb, out);
}